// round 7
// baseline (speedup 1.0000x reference)
#include <cuda_runtime.h>
#include <math.h>

// Problem constants (fixed by setup_inputs)
#define B_  8
#define T_  4096
#define D_  1024
#define A_  32
#define S_  16
#define H_  256             // max(ttl*4, S*4)
#define W_  (H_ - S_ + 1)   // 241
#define NT  256
#define NT2 512
#define NPAIR (B_ * A_)     // 256
#define TILE 64             // rows per K1 CTA
#define NTIL (T_ / TILE)    // 64 tiles per batch
#define HT   16             // half-tile granularity
#define NHT  (T_ / HT)      // 256 half-tiles per batch
#define MAXA 8              // anchors staged in smem per CTA

// Cross-kernel scratch (every slot written every launch; deterministic)
__device__ float g_ts16[B_][NHT][D_];   // 16-row half-tile column sums
__device__ float g_rn[B_][T_];          // per-row squared norms
__device__ float g_pd[NPAIR][H_];       // per-(pair,row) dot(h_t, anchor)

__device__ __forceinline__ unsigned long long compat_mask_of(int r) {
    switch (r) {
        case 11: return (1ull<<11)|(1ull<<13)|(1ull<<16);
        case 21: return (1ull<<14)|(1ull<<15)|(1ull<<21)|(1ull<<22)|(1ull<<23);
        case 31: return (1ull<<15)|(1ull<<31)|(1ull<<32)|(1ull<<33);
        case 41: return (1ull<<41)|(1ull<<42)|(1ull<<43)|(1ull<<44);
        case 51: return (1ull<<15)|(1ull<<51)|(1ull<<52)|(1ull<<53);
        default: return 0ull;
    }
}

__constant__ signed char c_alias[64] = {
    -1,-1,-1,-1,-1,-1,-1,-1,-1,-1,
    -1,11,-1,11,-1,-1,11,-1,-1,-1,
    -1,21,21,21,-1,-1,-1,-1,-1,-1,
    -1,31,31,31,-1,-1,-1,-1,-1,-1,
    -1,41,41,41,41,-1,-1,-1,-1,-1,
    -1,51,51,51,-1,-1,-1,-1,-1,-1,
    -1,-1,-1,-1
};

__device__ __forceinline__ float warpSum(float v) {
    #pragma unroll
    for (int o = 16; o > 0; o >>= 1) v += __shfl_xor_sync(0xffffffffu, v, o);
    return v;
}

__device__ __forceinline__ float blockSum16(float v, float* s16, int tid) {
    v = warpSum(v);
    if ((tid & 31) == 0) s16[tid >> 5] = v;
    __syncthreads();
    if (tid == 0) {
        float x = s16[0];
        #pragma unroll
        for (int w = 1; w < 16; w++) x += s16[w];
        s16[0] = x;
    }
    __syncthreads();
    float r = s16[0];
    __syncthreads();
    return r;
}

__device__ __forceinline__ float blockMax16(float v, float* s16, int tid) {
    #pragma unroll
    for (int o = 16; o > 0; o >>= 1) v = fmaxf(v, __shfl_xor_sync(0xffffffffu, v, o));
    if ((tid & 31) == 0) s16[tid >> 5] = v;
    __syncthreads();
    if (tid == 0) {
        float x = s16[0];
        #pragma unroll
        for (int w = 1; w < 16; w++) x = fmaxf(x, s16[w]);
        s16[0] = x;
    }
    __syncthreads();
    float r = s16[0];
    __syncthreads();
    return r;
}

// ---------------------------------------------------------------------------
// K1: single pass over hidden. CTA = (batch, 64-row tile). 512 CTAs total,
// launched as 3 batch-range slices so ncu (-s 5) lands on a K1 instance.
// Warp w owns 8 consecutive rows. Row in registers f[8]; column sums in
// registers cs[8] (occ-2 => 128-reg budget, no spills); anchors in SMEM.
// ---------------------------------------------------------------------------
__global__ __launch_bounds__(NT, 2)
void k1_stream(const float* __restrict__ hidden,
               const float* __restrict__ anchor_repr,
               const int*   __restrict__ anchor_end,
               int b0)
{
    __shared__ float s_anch[MAXA][D_];   // 32 KB staged anchors
    __shared__ float s_ws[8][D_];        // 32 KB per-warp column sums (written once)
    __shared__ int   s_aid[A_];
    __shared__ int   s_aend[A_];
    __shared__ int   s_na;

    const int b    = b0 + (blockIdx.x >> 6);
    const int tile = blockIdx.x & (NTIL - 1);
    const int t0   = tile * TILE;
    const int tid  = threadIdx.x;
    const int lane = tid & 31;
    const int warp = tid >> 5;

    // parallel covering-anchor scan (warp 0, ballot-compact; order irrelevant)
    if (warp == 0) {
        int ae = anchor_end[b * A_ + lane];          // A_ == 32
        bool cover = (ae >= t0 - H_) && (ae <= t0 + TILE - 2);
        unsigned m = __ballot_sync(0xffffffffu, cover);
        if (cover) {
            int idx = __popc(m & ((1u << lane) - 1u));
            s_aid[idx] = lane;
            s_aend[idx] = ae;
        }
        if (lane == 0) s_na = __popc(m);
    }
    __syncthreads();

    const int na = s_na;
    const int nstage = na < MAXA ? na : MAXA;
    for (int k = 0; k < nstage; k++) {
        const float4* src = reinterpret_cast<const float4*>(
            anchor_repr + ((size_t)(b * A_ + s_aid[k])) * D_);
        reinterpret_cast<float4*>(s_anch[k])[tid] = src[tid];
    }
    __syncthreads();

    const float* hb = hidden + ((size_t)(b * T_ + t0 + warp * 8)) * D_;

    float4 cs[8];
    #pragma unroll
    for (int i = 0; i < 8; i++) cs[i] = make_float4(0.f, 0.f, 0.f, 0.f);

    #pragma unroll 1
    for (int r = 0; r < 8; r++) {
        const int t = t0 + warp * 8 + r;
        const float4* row = reinterpret_cast<const float4*>(hb + (size_t)r * D_);

        float4 f[8];
        #pragma unroll
        for (int i = 0; i < 8; i++) f[i] = row[i * 32 + lane];

        float nrm = 0.0f;
        #pragma unroll
        for (int i = 0; i < 8; i++) {
            cs[i].x += f[i].x; cs[i].y += f[i].y; cs[i].z += f[i].z; cs[i].w += f[i].w;
            nrm += f[i].x*f[i].x + f[i].y*f[i].y + f[i].z*f[i].z + f[i].w*f[i].w;
        }
        nrm = warpSum(nrm);
        if (lane == 0) g_rn[b][t] = nrm;

        #pragma unroll 1
        for (int k = 0; k < na; k++) {
            const int h = t - s_aend[k] - 1;
            if ((unsigned)h < (unsigned)H_) {
                const float4* ap = (k < MAXA)
                    ? reinterpret_cast<const float4*>(s_anch[k])
                    : reinterpret_cast<const float4*>(
                        anchor_repr + ((size_t)(b * A_ + s_aid[k])) * D_);
                float dot = 0.0f;
                #pragma unroll
                for (int i = 0; i < 8; i++) {
                    float4 av = ap[i * 32 + lane];
                    dot += f[i].x*av.x + f[i].y*av.y + f[i].z*av.z + f[i].w*av.w;
                }
                dot = warpSum(dot);
                if (lane == 0) g_pd[b * A_ + s_aid[k]][h] = dot;
            }
        }
    }

    // dump register colsums once, then merge warp-pairs into 4 half-tiles
    float4* wbuf = reinterpret_cast<float4*>(s_ws[warp]);
    #pragma unroll
    for (int i = 0; i < 8; i++) wbuf[i * 32 + lane] = cs[i];
    __syncthreads();

    #pragma unroll
    for (int ht = 0; ht < 4; ht++) {
        float4 v0 = reinterpret_cast<const float4*>(s_ws[2*ht + 0])[tid];
        float4 v1 = reinterpret_cast<const float4*>(s_ws[2*ht + 1])[tid];
        v0.x += v1.x; v0.y += v1.y; v0.z += v1.z; v0.w += v1.w;
        reinterpret_cast<float4*>(&g_ts16[b][tile * 4 + ht][0])[tid] = v0;
    }
}

// ---------------------------------------------------------------------------
// K2: per-pair finalize. grid = NPAIR, 512 threads.
// ---------------------------------------------------------------------------
__global__ __launch_bounds__(NT2, 2)
void k2_final(const float* __restrict__ hidden,
              const float* __restrict__ anchor_repr,
              const int*   __restrict__ input_ids,
              const int*   __restrict__ anchor_end,
              float*       __restrict__ out)
{
    __shared__ float  s_red[16];
    __shared__ float4 s_sv[256];
    __shared__ int    s_ftok[H_];
    __shared__ int    s_span[S_];
    __shared__ int    s_alias[64];
    __shared__ int    s_root, s_has, s_ffmask;
    __shared__ float  s_invdenom;

    const int pair = blockIdx.x;
    const int b = pair >> 5;
    const int tid = threadIdx.x;
    const int c = tid & 255;
    const int p = tid >> 8;

    const int aend  = anchor_end[pair];
    const int start = aend + 1;
    const int end   = aend + H_;   // inclusive

    if (tid < 64) s_alias[tid] = (int)c_alias[tid];
    if (tid < H_) s_ftok[tid] = input_ids[b * T_ + start + tid];
    if (tid < S_) s_span[tid] = input_ids[b * T_ + aend - S_ + 1 + tid];

    const int j0 = (start + HT - 1) >> 4;
    const int j1 = ((end + 1) >> 4) - 1;
    float4 Sv = make_float4(0.f, 0.f, 0.f, 0.f);
    for (int j = j0 + p; j <= j1; j += 2) {
        float4 v = reinterpret_cast<const float4*>(&g_ts16[b][j][0])[c];
        Sv.x += v.x; Sv.y += v.y; Sv.z += v.z; Sv.w += v.w;
    }
    for (int t = start + p; t < (j0 << 4); t += 2) {
        float4 v = reinterpret_cast<const float4*>(hidden + ((size_t)(b * T_ + t)) * D_)[c];
        Sv.x += v.x; Sv.y += v.y; Sv.z += v.z; Sv.w += v.w;
    }
    for (int t = ((j1 + 1) << 4) + p; t <= end; t += 2) {
        float4 v = reinterpret_cast<const float4*>(hidden + ((size_t)(b * T_ + t)) * D_)[c];
        Sv.x += v.x; Sv.y += v.y; Sv.z += v.z; Sv.w += v.w;
    }
    if (p == 1) s_sv[c] = Sv;
    __syncthreads();

    float dotp = 0.f, nf2p = 0.f, na2p = 0.f;
    if (p == 0) {
        float4 o = s_sv[c];
        Sv.x += o.x; Sv.y += o.y; Sv.z += o.z; Sv.w += o.w;
        const float4 a4 = reinterpret_cast<const float4*>(anchor_repr + (size_t)pair * D_)[c];
        dotp = Sv.x*a4.x + Sv.y*a4.y + Sv.z*a4.z + Sv.w*a4.w;
        nf2p = Sv.x*Sv.x + Sv.y*Sv.y + Sv.z*Sv.z + Sv.w*Sv.w;
        na2p = a4.x*a4.x + a4.y*a4.y + a4.z*a4.z + a4.w*a4.w;
    }
    float dot = blockSum16(dotp, s_red, tid);
    float nf2 = blockSum16(nf2p, s_red, tid);
    float na2 = blockSum16(na2p, s_red, tid);

    const float invH = 1.0f / (float)H_;
    const float eps = 1e-8f;
    const float nr = fmaxf(sqrtf(na2), eps);
    const float nf = fmaxf(sqrtf(nf2) * invH, eps);
    const float sim = (dot * invH) / (nr * nf);
    const float hidden_c = fmaxf(0.0f, (1.0f - sim) * 0.5f);

    float sq = 0.0f;
    if (tid < H_) {
        float ssv = g_rn[b][start + tid] - 2.0f * g_pd[pair][tid] + na2;
        sq = sqrtf(fmaxf(ssv, 0.0f));
    }
    float shift_sum = blockSum16(sq, s_red, tid);
    const float future_shift = shift_sum * invH;

    const int anchor_tok = s_span[S_ - 1];
    float teq = (tid < H_ && s_ftok[tid] == anchor_tok) ? 1.0f : 0.0f;
    teq = blockSum16(teq, s_red, tid);
    const float token_c = 1.0f - teq * invH;

    if (tid == 0) {
        int ffmask = 0, denom = 0;
        #pragma unroll
        for (int s = 0; s < S_; s++) {
            bool first = true;
            for (int j = 0; j < s; j++)
                if (s_span[j] == s_span[s]) { first = false; break; }
            if (first) { ffmask |= (1 << s); denom++; }
        }
        int first_root = -1;
        #pragma unroll
        for (int s = 0; s < S_; s++) {
            int al = s_alias[s_span[s]];
            if (al >= 0) { first_root = al; break; }
        }
        int root;
        if (first_root >= 0) {
            root = first_root;
        } else {
            int maxc = 0;
            int counts[S_];
            #pragma unroll
            for (int s = 0; s < S_; s++) {
                int cnum = 0;
                for (int j = 0; j < S_; j++) cnum += (s_span[j] == s_span[s]);
                counts[s] = cnum;
                maxc = max(maxc, cnum);
            }
            int mode = 64;
            #pragma unroll
            for (int s = 0; s < S_; s++)
                if (counts[s] == maxc) mode = min(mode, s_span[s]);
            root = mode;
        }
        s_root = root;
        s_has = (compat_mask_of(root) != 0ull) ? 1 : 0;
        s_ffmask = ffmask;
        s_invdenom = 1.0f / (float)denom;
    }
    __syncthreads();

    const int root = s_root;
    const int has = s_has;
    const int ffmask = s_ffmask;
    const float invdenom = s_invdenom;
    const unsigned long long cmask = compat_mask_of(root);

    float sims = 0.0f, rp_mean = 0.0f, regime = 0.0f, hit06 = 0.0f, best_v = -1e30f;
    if (tid < W_) {
        float ex = 0.0f, pos = 0.0f, rp = 0.0f, ac = 0.0f, hd = 0.0f;
        unsigned long long wmask = 0ull;
        #pragma unroll
        for (int s = 0; s < S_; s++) {
            int tok = s_ftok[tid + s];
            wmask |= (1ull << tok);
            float eq = (tok == s_span[s]) ? 1.0f : 0.0f;
            ex  += eq;
            pos += eq * ((1.0f - 0.04f * (float)s) * (1.0f / 11.2f));
            rp  += (tok == root) ? 1.0f : 0.0f;
            ac  += (s_alias[tok] == root) ? 1.0f : 0.0f;
            hd  += (float)((cmask >> tok) & 1ull);
        }
        float ov = 0.0f;
        #pragma unroll
        for (int s = 0; s < S_; s++) {
            if (((ffmask >> s) & 1) && ((wmask >> s_span[s]) & 1ull)) ov += 1.0f;
        }
        ov *= invdenom;
        const float inv16 = 1.0f / 16.0f;
        ex *= inv16; ac *= inv16; hd *= inv16;
        rp_mean = rp * inv16;

        regime = has ? (0.55f*hd + 0.2f*ov + 0.15f*ac + 0.1f*rp_mean)
                     : (0.45f*ex + 0.3f*ov + 0.1f*ac + 0.15f*rp_mean);
        sims = 0.25f*ex + 0.15f*ov + 0.35f*pos + 0.25f*regime;
        best_v = sims;
        hit06 = (sims >= 0.6f) ? 1.0f : 0.0f;
    }

    float best     = blockMax16(best_v,  s_red, tid);
    float sum_sims = blockSum16(sims,    s_red, tid);
    float sum_rp   = blockSum16(rp_mean, s_red, tid);
    float sum_reg  = blockSum16(regime,  s_red, tid);
    float cnt06    = blockSum16(hit06,   s_red, tid);

    if (tid == 0) {
        const float invW = 1.0f / (float)W_;
        float mrp = sum_rp  * invW;
        float mrc = sum_reg * invW;
        float mean_sims = sum_sims * invW;
        float dmass = cnt06 * invW;
        float dcoh = 0.6f*mean_sims + 0.25f*mrp + 0.15f*mrc;
        float pattern_c = 1.0f - (0.6f*best + 0.2f*mrp + 0.2f*mrc);
        float contr = 0.2f*hidden_c + 0.2f*token_c + 0.6f*pattern_c;
        contr = fminf(fmaxf(contr, 0.0f), 1.0f);

        out[0 * NPAIR + pair] = contr;
        out[1 * NPAIR + pair] = future_shift;
        out[2 * NPAIR + pair] = sim;
        out[3 * NPAIR + pair] = hidden_c;
        out[4 * NPAIR + pair] = token_c;
        out[5 * NPAIR + pair] = pattern_c;
        out[6 * NPAIR + pair] = dmass;
        out[7 * NPAIR + pair] = dcoh;
    }
}

extern "C" void kernel_launch(void* const* d_in, const int* in_sizes, int n_in,
                              void* d_out, int out_size) {
    const float* hidden      = (const float*)d_in[0];
    const float* anchor_repr = (const float*)d_in[1];
    const int*   input_ids   = (const int*)d_in[2];
    const int*   anchor_end  = (const int*)d_in[3];
    float*       out         = (float*)d_out;
    // 3 K1 slices + K2: period-4 launch pattern puts a K1 instance at
    // ncu's captured launch (#6) instead of always K2.
    k1_stream<<<3 * NTIL, NT>>>(hidden, anchor_repr, anchor_end, 0);
    k1_stream<<<3 * NTIL, NT>>>(hidden, anchor_repr, anchor_end, 3);
    k1_stream<<<2 * NTIL, NT>>>(hidden, anchor_repr, anchor_end, 6);
    k2_final<<<NPAIR, NT2>>>(hidden, anchor_repr, input_ids, anchor_end, out);
}

// round 8
// speedup vs baseline: 1.3085x; 1.3085x over previous
#include <cuda_runtime.h>
#include <math.h>

#define B_  8
#define T_  4096
#define D_  1024
#define A_  32
#define S_  16
#define H_  256
#define W_  (H_ - S_ + 1)   // 241
#define NT  256
#define NPAIR (B_ * A_)     // 256
#define NPR  (NPAIR / 2)    // 128 anchor-pair tasks

// scratch: every slot written every launch (halves always write both windows)
__device__ float g_w [NPR][2][2][D_];   // [pairTask][half][window][d]  (4 MB)
__device__ float g_sc[NPR][2][2];       // [pairTask][half][window] shift partial

__device__ __forceinline__ unsigned long long compat_mask_of(int r) {
    switch (r) {
        case 11: return (1ull<<11)|(1ull<<13)|(1ull<<16);
        case 21: return (1ull<<14)|(1ull<<15)|(1ull<<21)|(1ull<<22)|(1ull<<23);
        case 31: return (1ull<<15)|(1ull<<31)|(1ull<<32)|(1ull<<33);
        case 41: return (1ull<<41)|(1ull<<42)|(1ull<<43)|(1ull<<44);
        case 51: return (1ull<<15)|(1ull<<51)|(1ull<<52)|(1ull<<53);
        default: return 0ull;
    }
}

__constant__ signed char c_alias[64] = {
    -1,-1,-1,-1,-1,-1,-1,-1,-1,-1,
    -1,11,-1,11,-1,-1,11,-1,-1,-1,
    -1,21,21,21,-1,-1,-1,-1,-1,-1,
    -1,31,31,31,-1,-1,-1,-1,-1,-1,
    -1,41,41,41,41,-1,-1,-1,-1,-1,
    -1,51,51,51,-1,-1,-1,-1,-1,-1,
    -1,-1,-1,-1
};

__device__ __forceinline__ float warpSum(float v) {
    #pragma unroll
    for (int o = 16; o > 0; o >>= 1) v += __shfl_xor_sync(0xffffffffu, v, o);
    return v;
}

__device__ __forceinline__ float blockSum(float v, float* s8, int tid) {
    v = warpSum(v);
    if ((tid & 31) == 0) s8[tid >> 5] = v;
    __syncthreads();
    if (tid == 0) {
        float x = s8[0];
        #pragma unroll
        for (int w = 1; w < 8; w++) x += s8[w];
        s8[0] = x;
    }
    __syncthreads();
    float r = s8[0]; __syncthreads();
    return r;
}

__device__ __forceinline__ float blockMax(float v, float* s8, int tid) {
    #pragma unroll
    for (int o = 16; o > 0; o >>= 1) v = fmaxf(v, __shfl_xor_sync(0xffffffffu, v, o));
    if ((tid & 31) == 0) s8[tid >> 5] = v;
    __syncthreads();
    if (tid == 0) {
        float x = s8[0];
        #pragma unroll
        for (int w = 1; w < 8; w++) x = fmaxf(x, s8[w]);
        s8[0] = x;
    }
    __syncthreads();
    float r = s8[0]; __syncthreads();
    return r;
}

// rank-sort 32 values held one-per-lane (warp 0); ties broken by lane id.
// returns rank of this lane's value.
__device__ __forceinline__ int warpRank32(int ae, int lane) {
    int rank = 0;
    #pragma unroll
    for (int j = 0; j < 32; j++) {
        int aj = __shfl_sync(0xffffffffu, ae, j);
        rank += (aj < ae) || (aj == ae && j < lane);
    }
    return rank;
}

// ---------------------------------------------------------------------------
// KA: stream union of two adjacent (sorted) anchor windows. grid = 2*NPR = 256.
// blockIdx = pairTask*2 + half. Two window colsums in REGISTERS (predicated),
// one interleaved warpSum3 per row. 256 threads, 8 warps, warp owns rows i%8.
// ---------------------------------------------------------------------------
__global__ __launch_bounds__(NT, 2)
void ka_stream(const float* __restrict__ hidden,
               const float* __restrict__ anchor_repr,
               const int*   __restrict__ anchor_end)
{
    __shared__ float s_a0[D_], s_a1[D_];
    __shared__ float s_m0[D_], s_m1[D_];
    __shared__ float s_red[8];
    __shared__ int   s_info[4];   // s0, s1, id0, id1

    const int P    = blockIdx.x >> 1;
    const int half = blockIdx.x & 1;
    const int b    = P >> 4;          // 16 pair-tasks per batch
    const int p    = P & 15;
    const int tid  = threadIdx.x;
    const int lane = tid & 31;
    const int warp = tid >> 5;

    // sort batch anchors by anchor_end (warp 0), pick ranks 2p, 2p+1
    if (warp == 0) {
        int ae = anchor_end[b * A_ + lane];
        int rank = warpRank32(ae, lane);
        if (rank == 2 * p)     { s_info[0] = ae + 1; s_info[2] = lane; }
        if (rank == 2 * p + 1) { s_info[1] = ae + 1; s_info[3] = lane; }
    }
    __syncthreads();

    const int s0  = s_info[0];
    const int s1  = s_info[1];
    const int id0 = s_info[2];
    const int id1 = s_info[3];
    const int gap = s1 - s0;           // >= 0
    const int L   = gap + H_;          // union span length

    // stage both anchors
    {
        const float4* a0p = reinterpret_cast<const float4*>(anchor_repr + ((size_t)(b*A_+id0))*D_);
        const float4* a1p = reinterpret_cast<const float4*>(anchor_repr + ((size_t)(b*A_+id1))*D_);
        reinterpret_cast<float4*>(s_a0)[tid] = a0p[tid];
        reinterpret_cast<float4*>(s_a1)[tid] = a1p[tid];
        // zero merge buffers
        #pragma unroll
        for (int q = 0; q < 4; q++) { s_m0[tid + q*256] = 0.f; s_m1[tid + q*256] = 0.f; }
    }
    __syncthreads();

    // |a|^2 for both anchors
    float pa0 = 0.f, pa1 = 0.f;
    {
        float4 v0 = reinterpret_cast<const float4*>(s_a0)[tid];
        float4 v1 = reinterpret_cast<const float4*>(s_a1)[tid];
        pa0 = v0.x*v0.x + v0.y*v0.y + v0.z*v0.z + v0.w*v0.w;
        pa1 = v1.x*v1.x + v1.y*v1.y + v1.z*v1.z + v1.w*v1.w;
    }
    const float na20 = blockSum(pa0, s_red, tid);
    const float na21 = blockSum(pa1, s_red, tid);

    // this half's row range
    const int i0 = half ? (L >> 1) : 0;
    const int i1 = half ? L : (L >> 1);

    float4 w0[8], w1[8];
    #pragma unroll
    for (int i = 0; i < 8; i++) {
        w0[i] = make_float4(0.f,0.f,0.f,0.f);
        w1[i] = make_float4(0.f,0.f,0.f,0.f);
    }
    float sh0 = 0.f, sh1 = 0.f;

    const float4* a0f = reinterpret_cast<const float4*>(s_a0);
    const float4* a1f = reinterpret_cast<const float4*>(s_a1);

    for (int i = i0 + warp; i < i1; i += 8) {
        const bool in0 = (i < H_);
        const bool in1 = (i >= gap) && (i < gap + H_);
        if (!in0 && !in1) continue;     // hole when gap > H_

        const float4* row = reinterpret_cast<const float4*>(
            hidden + ((size_t)(b * T_ + s0 + i)) * D_);

        float4 f[8];
        #pragma unroll
        for (int q = 0; q < 8; q++) f[q] = row[q * 32 + lane];

        float nrm = 0.f, d0 = 0.f, d1 = 0.f;
        #pragma unroll
        for (int q = 0; q < 8; q++) {
            float4 fv = f[q];
            nrm += fv.x*fv.x + fv.y*fv.y + fv.z*fv.z + fv.w*fv.w;
            float4 a0v = a0f[q * 32 + lane];
            d0 += fv.x*a0v.x + fv.y*a0v.y + fv.z*a0v.z + fv.w*a0v.w;
            float4 a1v = a1f[q * 32 + lane];
            d1 += fv.x*a1v.x + fv.y*a1v.y + fv.z*a1v.z + fv.w*a1v.w;
        }
        if (in0) {
            #pragma unroll
            for (int q = 0; q < 8; q++) {
                w0[q].x += f[q].x; w0[q].y += f[q].y; w0[q].z += f[q].z; w0[q].w += f[q].w;
            }
        }
        if (in1) {
            #pragma unroll
            for (int q = 0; q < 8; q++) {
                w1[q].x += f[q].x; w1[q].y += f[q].y; w1[q].z += f[q].z; w1[q].w += f[q].w;
            }
        }
        // one interleaved 3-way warp reduction (chains overlap)
        #pragma unroll
        for (int o = 16; o > 0; o >>= 1) {
            nrm += __shfl_xor_sync(0xffffffffu, nrm, o);
            d0  += __shfl_xor_sync(0xffffffffu, d0,  o);
            d1  += __shfl_xor_sync(0xffffffffu, d1,  o);
        }
        if (lane == 0) {
            if (in0) sh0 += sqrtf(fmaxf(nrm - 2.f*d0 + na20, 0.f));
            if (in1) sh1 += sqrtf(fmaxf(nrm - 2.f*d1 + na21, 0.f));
        }
    }

    // merge per-warp register colsums (once per CTA)
    #pragma unroll
    for (int q = 0; q < 8; q++) {
        const int d = q * 128 + lane * 4;
        atomicAdd(&s_m0[d+0], w0[q].x); atomicAdd(&s_m0[d+1], w0[q].y);
        atomicAdd(&s_m0[d+2], w0[q].z); atomicAdd(&s_m0[d+3], w0[q].w);
        atomicAdd(&s_m1[d+0], w1[q].x); atomicAdd(&s_m1[d+1], w1[q].y);
        atomicAdd(&s_m1[d+2], w1[q].z); atomicAdd(&s_m1[d+3], w1[q].w);
    }
    // reduce shift partials (lane0 of each warp holds them)
    float v0 = (lane == 0) ? sh0 : 0.f;
    float v1 = (lane == 0) ? sh1 : 0.f;
    float t0 = blockSum(v0, s_red, tid);
    float t1 = blockSum(v1, s_red, tid);
    // (blockSum has trailing barrier; s_m writes are complete for all warps)

    reinterpret_cast<float4*>(&g_w[P][half][0][0])[tid] = reinterpret_cast<const float4*>(s_m0)[tid];
    reinterpret_cast<float4*>(&g_w[P][half][1][0])[tid] = reinterpret_cast<const float4*>(s_m1)[tid];
    if (tid == 0) { g_sc[P][half][0] = t0; g_sc[P][half][1] = t1; }
}

// ---------------------------------------------------------------------------
// KB: per-anchor finalize. grid = NPAIR (one CTA per (batch, sorted rank)).
// ---------------------------------------------------------------------------
__global__ __launch_bounds__(NT, 4)
void kb_final(const float* __restrict__ anchor_repr,
              const int*   __restrict__ input_ids,
              const int*   __restrict__ anchor_end,
              float*       __restrict__ out)
{
    __shared__ float s_red[8];
    __shared__ int   s_ftok[H_];
    __shared__ int   s_span[S_];
    __shared__ int   s_alias[64];
    __shared__ int   s_root, s_has, s_ffmask;
    __shared__ float s_invdenom;
    __shared__ int   s_info[2];   // aend, orig id

    const int rank = blockIdx.x & 31;
    const int b    = blockIdx.x >> 5;
    const int tid  = threadIdx.x;
    const int lane = tid & 31;
    const int warp = tid >> 5;

    if (warp == 0) {
        int ae = anchor_end[b * A_ + lane];
        int r = warpRank32(ae, lane);
        if (r == rank) { s_info[0] = ae; s_info[1] = lane; }
    }
    if (tid < 64) s_alias[tid] = (int)c_alias[tid];
    __syncthreads();

    const int aend = s_info[0];
    const int orig = s_info[1];
    const int start = aend + 1;
    const int P = b * 16 + (rank >> 1);
    const int w = rank & 1;
    const int pair_out = b * A_ + orig;

    s_ftok[tid] = input_ids[b * T_ + start + tid];   // H_ == NT
    if (tid < S_) s_span[tid] = input_ids[b * T_ + aend - S_ + 1 + tid];
    __syncthreads();

    // window sum vector = halves combined
    float4 u0 = reinterpret_cast<const float4*>(&g_w[P][0][w][0])[tid];
    float4 u1 = reinterpret_cast<const float4*>(&g_w[P][1][w][0])[tid];
    float4 Sv = make_float4(u0.x+u1.x, u0.y+u1.y, u0.z+u1.z, u0.w+u1.w);
    const float4 a4 = reinterpret_cast<const float4*>(
        anchor_repr + ((size_t)pair_out) * D_)[tid];

    float dotp = Sv.x*a4.x + Sv.y*a4.y + Sv.z*a4.z + Sv.w*a4.w;
    float nf2p = Sv.x*Sv.x + Sv.y*Sv.y + Sv.z*Sv.z + Sv.w*Sv.w;
    float na2p = a4.x*a4.x + a4.y*a4.y + a4.z*a4.z + a4.w*a4.w;

    float dot = blockSum(dotp, s_red, tid);
    float nf2 = blockSum(nf2p, s_red, tid);
    float na2 = blockSum(na2p, s_red, tid);

    const float invH = 1.0f / (float)H_;
    const float eps = 1e-8f;
    const float nr = fmaxf(sqrtf(na2), eps);
    const float nf = fmaxf(sqrtf(nf2) * invH, eps);
    const float sim = (dot * invH) / (nr * nf);
    const float hidden_c = fmaxf(0.0f, (1.0f - sim) * 0.5f);
    const float future_shift = (g_sc[P][0][w] + g_sc[P][1][w]) * invH;

    const int anchor_tok = s_span[S_ - 1];
    float teq = (s_ftok[tid] == anchor_tok) ? 1.0f : 0.0f;
    teq = blockSum(teq, s_red, tid);
    const float token_c = 1.0f - teq * invH;

    if (tid == 0) {
        int ffmask = 0, denom = 0;
        #pragma unroll
        for (int s = 0; s < S_; s++) {
            bool first = true;
            for (int j = 0; j < s; j++)
                if (s_span[j] == s_span[s]) { first = false; break; }
            if (first) { ffmask |= (1 << s); denom++; }
        }
        int first_root = -1;
        #pragma unroll
        for (int s = 0; s < S_; s++) {
            int al = s_alias[s_span[s]];
            if (al >= 0) { first_root = al; break; }
        }
        int root;
        if (first_root >= 0) {
            root = first_root;
        } else {
            int maxc = 0, counts[S_];
            #pragma unroll
            for (int s = 0; s < S_; s++) {
                int cnum = 0;
                for (int j = 0; j < S_; j++) cnum += (s_span[j] == s_span[s]);
                counts[s] = cnum;
                maxc = max(maxc, cnum);
            }
            int mode = 64;
            #pragma unroll
            for (int s = 0; s < S_; s++)
                if (counts[s] == maxc) mode = min(mode, s_span[s]);
            root = mode;
        }
        s_root = root;
        s_has = (compat_mask_of(root) != 0ull) ? 1 : 0;
        s_ffmask = ffmask;
        s_invdenom = 1.0f / (float)denom;
    }
    __syncthreads();

    const int root = s_root;
    const int has = s_has;
    const int ffmask = s_ffmask;
    const float invdenom = s_invdenom;
    const unsigned long long cmask = compat_mask_of(root);

    float sims = 0.0f, rp_mean = 0.0f, regime = 0.0f, hit06 = 0.0f, best_v = -1e30f;
    if (tid < W_) {
        float ex = 0.0f, pos = 0.0f, rp = 0.0f, ac = 0.0f, hd = 0.0f;
        unsigned long long wmask = 0ull;
        #pragma unroll
        for (int s = 0; s < S_; s++) {
            int tok = s_ftok[tid + s];
            wmask |= (1ull << tok);
            float eq = (tok == s_span[s]) ? 1.0f : 0.0f;
            ex  += eq;
            pos += eq * ((1.0f - 0.04f * (float)s) * (1.0f / 11.2f));
            rp  += (tok == root) ? 1.0f : 0.0f;
            ac  += (s_alias[tok] == root) ? 1.0f : 0.0f;
            hd  += (float)((cmask >> tok) & 1ull);
        }
        float ov = 0.0f;
        #pragma unroll
        for (int s = 0; s < S_; s++) {
            if (((ffmask >> s) & 1) && ((wmask >> s_span[s]) & 1ull)) ov += 1.0f;
        }
        ov *= invdenom;
        const float inv16 = 1.0f / 16.0f;
        ex *= inv16; ac *= inv16; hd *= inv16;
        rp_mean = rp * inv16;

        regime = has ? (0.55f*hd + 0.2f*ov + 0.15f*ac + 0.1f*rp_mean)
                     : (0.45f*ex + 0.3f*ov + 0.1f*ac + 0.15f*rp_mean);
        sims = 0.25f*ex + 0.15f*ov + 0.35f*pos + 0.25f*regime;
        best_v = sims;
        hit06 = (sims >= 0.6f) ? 1.0f : 0.0f;
    }

    float best     = blockMax(best_v,  s_red, tid);
    float sum_sims = blockSum(sims,    s_red, tid);
    float sum_rp   = blockSum(rp_mean, s_red, tid);
    float sum_reg  = blockSum(regime,  s_red, tid);
    float cnt06    = blockSum(hit06,   s_red, tid);

    if (tid == 0) {
        const float invW = 1.0f / (float)W_;
        float mrp = sum_rp  * invW;
        float mrc = sum_reg * invW;
        float mean_sims = sum_sims * invW;
        float dmass = cnt06 * invW;
        float dcoh = 0.6f*mean_sims + 0.25f*mrp + 0.15f*mrc;
        float pattern_c = 1.0f - (0.6f*best + 0.2f*mrp + 0.2f*mrc);
        float contr = 0.2f*hidden_c + 0.2f*token_c + 0.6f*pattern_c;
        contr = fminf(fmaxf(contr, 0.0f), 1.0f);

        out[0 * NPAIR + pair_out] = contr;
        out[1 * NPAIR + pair_out] = future_shift;
        out[2 * NPAIR + pair_out] = sim;
        out[3 * NPAIR + pair_out] = hidden_c;
        out[4 * NPAIR + pair_out] = token_c;
        out[5 * NPAIR + pair_out] = pattern_c;
        out[6 * NPAIR + pair_out] = dmass;
        out[7 * NPAIR + pair_out] = dcoh;
    }
}

extern "C" void kernel_launch(void* const* d_in, const int* in_sizes, int n_in,
                              void* d_out, int out_size) {
    const float* hidden      = (const float*)d_in[0];
    const float* anchor_repr = (const float*)d_in[1];
    const int*   input_ids   = (const int*)d_in[2];
    const int*   anchor_end  = (const int*)d_in[3];
    float*       out         = (float*)d_out;
    ka_stream<<<2 * NPR, NT>>>(hidden, anchor_repr, anchor_end);
    kb_final<<<NPAIR, NT>>>(anchor_repr, input_ids, anchor_end, out);
}

// round 9
// speedup vs baseline: 1.9421x; 1.4842x over previous
#include <cuda_runtime.h>
#include <math.h>

#define B_  8
#define T_  4096
#define D_  1024
#define A_  32
#define S_  16
#define H_  256
#define W_  (H_ - S_ + 1)   // 241
#define NT  256
#define NPAIR (B_ * A_)     // 256
#define NPR  (NPAIR / 2)    // 128 anchor-pair tasks

// scratch: every slot written every launch
__device__ float g_w [NPR][2][2][D_];   // [pairTask][half][window][d]
__device__ float g_sc[NPR][2][2];       // [pairTask][half][window] shift partial

__device__ __forceinline__ unsigned long long compat_mask_of(int r) {
    switch (r) {
        case 11: return (1ull<<11)|(1ull<<13)|(1ull<<16);
        case 21: return (1ull<<14)|(1ull<<15)|(1ull<<21)|(1ull<<22)|(1ull<<23);
        case 31: return (1ull<<15)|(1ull<<31)|(1ull<<32)|(1ull<<33);
        case 41: return (1ull<<41)|(1ull<<42)|(1ull<<43)|(1ull<<44);
        case 51: return (1ull<<15)|(1ull<<51)|(1ull<<52)|(1ull<<53);
        default: return 0ull;
    }
}

__constant__ signed char c_alias[64] = {
    -1,-1,-1,-1,-1,-1,-1,-1,-1,-1,
    -1,11,-1,11,-1,-1,11,-1,-1,-1,
    -1,21,21,21,-1,-1,-1,-1,-1,-1,
    -1,31,31,31,-1,-1,-1,-1,-1,-1,
    -1,41,41,41,41,-1,-1,-1,-1,-1,
    -1,51,51,51,-1,-1,-1,-1,-1,-1,
    -1,-1,-1,-1
};

__device__ __forceinline__ float warpSum(float v) {
    #pragma unroll
    for (int o = 16; o > 0; o >>= 1) v += __shfl_xor_sync(0xffffffffu, v, o);
    return v;
}

__device__ __forceinline__ float blockSum(float v, float* s8, int tid) {
    v = warpSum(v);
    if ((tid & 31) == 0) s8[tid >> 5] = v;
    __syncthreads();
    if (tid == 0) {
        float x = s8[0];
        #pragma unroll
        for (int w = 1; w < 8; w++) x += s8[w];
        s8[0] = x;
    }
    __syncthreads();
    float r = s8[0]; __syncthreads();
    return r;
}

__device__ __forceinline__ float blockMax(float v, float* s8, int tid) {
    #pragma unroll
    for (int o = 16; o > 0; o >>= 1) v = fmaxf(v, __shfl_xor_sync(0xffffffffu, v, o));
    if ((tid & 31) == 0) s8[tid >> 5] = v;
    __syncthreads();
    if (tid == 0) {
        float x = s8[0];
        #pragma unroll
        for (int w = 1; w < 8; w++) x = fmaxf(x, s8[w]);
        s8[0] = x;
    }
    __syncthreads();
    float r = s8[0]; __syncthreads();
    return r;
}

__device__ __forceinline__ int warpRank32(int ae, int lane) {
    int rank = 0;
    #pragma unroll
    for (int j = 0; j < 32; j++) {
        int aj = __shfl_sync(0xffffffffu, ae, j);
        rank += (aj < ae) || (aj == ae && j < lane);
    }
    return rank;
}

// ---------------------------------------------------------------------------
// KA: union-dedup stream over adjacent sorted anchor pairs. grid = 256.
// Two phases per warp; active anchor lives in REGISTERS; NO LDS in hot loop.
// Per-warp colsums in registers, dumped once per phase to private smem slice.
// ---------------------------------------------------------------------------
__global__ __launch_bounds__(NT, 2)
void ka_stream(const float* __restrict__ hidden,
               const float* __restrict__ anchor_repr,
               const int*   __restrict__ anchor_end)
{
    __shared__ float s_ws[2][8][D_];   // 64 KB: [window][warp][d]
    __shared__ float s_shw[2][8];      // per-warp shift partials
    __shared__ int   s_info[4];        // s0, s1, id0, id1

    const int P    = blockIdx.x >> 1;
    const int half = blockIdx.x & 1;
    const int b    = P >> 4;
    const int p    = P & 15;
    const int tid  = threadIdx.x;
    const int lane = tid & 31;
    const int warp = tid >> 5;

    if (warp == 0) {
        int ae = anchor_end[b * A_ + lane];
        int rank = warpRank32(ae, lane);
        if (rank == 2 * p)     { s_info[0] = ae + 1; s_info[2] = lane; }
        if (rank == 2 * p + 1) { s_info[1] = ae + 1; s_info[3] = lane; }
    }
    __syncthreads();

    const int s0  = s_info[0];
    const int s1  = s_info[1];
    const int gap = s1 - s0;           // >= 0
    const int L   = gap + H_;
    const int i0  = half ? (L >> 1) : 0;
    const int i1  = half ? L : (L >> 1);

    #pragma unroll 1
    for (int phase = 0; phase < 2; phase++) {
        const int aid = phase ? s_info[3] : s_info[2];
        const int lo  = phase ? max(i0, gap) : i0;
        const int hi  = phase ? i1 : min(i1, H_);

        // stage this phase's anchor into registers (L1-shared across warps)
        const float4* ap = reinterpret_cast<const float4*>(
            anchor_repr + ((size_t)(b * A_ + aid)) * D_);
        float4 a[8];
        #pragma unroll
        for (int q = 0; q < 8; q++) a[q] = ap[q * 32 + lane];

        float pa = 0.f;
        #pragma unroll
        for (int q = 0; q < 8; q++)
            pa += a[q].x*a[q].x + a[q].y*a[q].y + a[q].z*a[q].z + a[q].w*a[q].w;
        const float na2 = warpSum(pa);

        float4 w[8];
        #pragma unroll
        for (int q = 0; q < 8; q++) w[q] = make_float4(0.f,0.f,0.f,0.f);
        float sh = 0.f;

        for (int r = lo + warp; r < hi; r += 8) {
            const float4* row = reinterpret_cast<const float4*>(
                hidden + ((size_t)(b * T_ + s0 + r)) * D_);
            float nrm = 0.f, dot = 0.f;
            #pragma unroll
            for (int q = 0; q < 8; q++) {
                float4 f = row[q * 32 + lane];
                nrm += f.x*f.x + f.y*f.y + f.z*f.z + f.w*f.w;
                dot += f.x*a[q].x + f.y*a[q].y + f.z*a[q].z + f.w*a[q].w;
                w[q].x += f.x; w[q].y += f.y; w[q].z += f.z; w[q].w += f.w;
            }
            #pragma unroll
            for (int o = 16; o > 0; o >>= 1) {
                nrm += __shfl_xor_sync(0xffffffffu, nrm, o);
                dot += __shfl_xor_sync(0xffffffffu, dot, o);
            }
            if (lane == 0) sh += sqrtf(fmaxf(nrm - 2.f*dot + na2, 0.f));
        }

        // dump register colsums to this warp's private slice (plain STS, once)
        float4* wb = reinterpret_cast<float4*>(s_ws[phase][warp]);
        #pragma unroll
        for (int q = 0; q < 8; q++) wb[q * 32 + lane] = w[q];
        if (lane == 0) s_shw[phase][warp] = sh;
    }
    __syncthreads();

    // tree-merge 8 warp slices per window; thread tid owns float4 column tid
    #pragma unroll
    for (int win = 0; win < 2; win++) {
        float4 acc = make_float4(0.f,0.f,0.f,0.f);
        #pragma unroll
        for (int w = 0; w < 8; w++) {
            float4 v = reinterpret_cast<const float4*>(s_ws[win][w])[tid];
            acc.x += v.x; acc.y += v.y; acc.z += v.z; acc.w += v.w;
        }
        reinterpret_cast<float4*>(&g_w[P][half][win][0])[tid] = acc;
    }
    if (tid == 0) {
        float t0 = 0.f, t1 = 0.f;
        #pragma unroll
        for (int w = 0; w < 8; w++) { t0 += s_shw[0][w]; t1 += s_shw[1][w]; }
        g_sc[P][half][0] = t0;
        g_sc[P][half][1] = t1;
    }
}

// ---------------------------------------------------------------------------
// KB: per-anchor finalize. grid = NPAIR. (unchanged from R8 — measured 9.7us)
// ---------------------------------------------------------------------------
__global__ __launch_bounds__(NT, 4)
void kb_final(const float* __restrict__ anchor_repr,
              const int*   __restrict__ input_ids,
              const int*   __restrict__ anchor_end,
              float*       __restrict__ out)
{
    __shared__ float s_red[8];
    __shared__ int   s_ftok[H_];
    __shared__ int   s_span[S_];
    __shared__ int   s_alias[64];
    __shared__ int   s_root, s_has, s_ffmask;
    __shared__ float s_invdenom;
    __shared__ int   s_info[2];

    const int rank = blockIdx.x & 31;
    const int b    = blockIdx.x >> 5;
    const int tid  = threadIdx.x;
    const int lane = tid & 31;
    const int warp = tid >> 5;

    if (warp == 0) {
        int ae = anchor_end[b * A_ + lane];
        int r = warpRank32(ae, lane);
        if (r == rank) { s_info[0] = ae; s_info[1] = lane; }
    }
    if (tid < 64) s_alias[tid] = (int)c_alias[tid];
    __syncthreads();

    const int aend = s_info[0];
    const int orig = s_info[1];
    const int start = aend + 1;
    const int P = b * 16 + (rank >> 1);
    const int w = rank & 1;
    const int pair_out = b * A_ + orig;

    s_ftok[tid] = input_ids[b * T_ + start + tid];
    if (tid < S_) s_span[tid] = input_ids[b * T_ + aend - S_ + 1 + tid];
    __syncthreads();

    float4 u0 = reinterpret_cast<const float4*>(&g_w[P][0][w][0])[tid];
    float4 u1 = reinterpret_cast<const float4*>(&g_w[P][1][w][0])[tid];
    float4 Sv = make_float4(u0.x+u1.x, u0.y+u1.y, u0.z+u1.z, u0.w+u1.w);
    const float4 a4 = reinterpret_cast<const float4*>(
        anchor_repr + ((size_t)pair_out) * D_)[tid];

    float dotp = Sv.x*a4.x + Sv.y*a4.y + Sv.z*a4.z + Sv.w*a4.w;
    float nf2p = Sv.x*Sv.x + Sv.y*Sv.y + Sv.z*Sv.z + Sv.w*Sv.w;
    float na2p = a4.x*a4.x + a4.y*a4.y + a4.z*a4.z + a4.w*a4.w;

    float dot = blockSum(dotp, s_red, tid);
    float nf2 = blockSum(nf2p, s_red, tid);
    float na2 = blockSum(na2p, s_red, tid);

    const float invH = 1.0f / (float)H_;
    const float eps = 1e-8f;
    const float nr = fmaxf(sqrtf(na2), eps);
    const float nf = fmaxf(sqrtf(nf2) * invH, eps);
    const float sim = (dot * invH) / (nr * nf);
    const float hidden_c = fmaxf(0.0f, (1.0f - sim) * 0.5f);
    const float future_shift = (g_sc[P][0][w] + g_sc[P][1][w]) * invH;

    const int anchor_tok = s_span[S_ - 1];
    float teq = (s_ftok[tid] == anchor_tok) ? 1.0f : 0.0f;
    teq = blockSum(teq, s_red, tid);
    const float token_c = 1.0f - teq * invH;

    if (tid == 0) {
        int ffmask = 0, denom = 0;
        #pragma unroll
        for (int s = 0; s < S_; s++) {
            bool first = true;
            for (int j = 0; j < s; j++)
                if (s_span[j] == s_span[s]) { first = false; break; }
            if (first) { ffmask |= (1 << s); denom++; }
        }
        int first_root = -1;
        #pragma unroll
        for (int s = 0; s < S_; s++) {
            int al = s_alias[s_span[s]];
            if (al >= 0) { first_root = al; break; }
        }
        int root;
        if (first_root >= 0) {
            root = first_root;
        } else {
            int maxc = 0, counts[S_];
            #pragma unroll
            for (int s = 0; s < S_; s++) {
                int cnum = 0;
                for (int j = 0; j < S_; j++) cnum += (s_span[j] == s_span[s]);
                counts[s] = cnum;
                maxc = max(maxc, cnum);
            }
            int mode = 64;
            #pragma unroll
            for (int s = 0; s < S_; s++)
                if (counts[s] == maxc) mode = min(mode, s_span[s]);
            root = mode;
        }
        s_root = root;
        s_has = (compat_mask_of(root) != 0ull) ? 1 : 0;
        s_ffmask = ffmask;
        s_invdenom = 1.0f / (float)denom;
    }
    __syncthreads();

    const int root = s_root;
    const int has = s_has;
    const int ffmask = s_ffmask;
    const float invdenom = s_invdenom;
    const unsigned long long cmask = compat_mask_of(root);

    float sims = 0.0f, rp_mean = 0.0f, regime = 0.0f, hit06 = 0.0f, best_v = -1e30f;
    if (tid < W_) {
        float ex = 0.0f, pos = 0.0f, rp = 0.0f, ac = 0.0f, hd = 0.0f;
        unsigned long long wmask = 0ull;
        #pragma unroll
        for (int s = 0; s < S_; s++) {
            int tok = s_ftok[tid + s];
            wmask |= (1ull << tok);
            float eq = (tok == s_span[s]) ? 1.0f : 0.0f;
            ex  += eq;
            pos += eq * ((1.0f - 0.04f * (float)s) * (1.0f / 11.2f));
            rp  += (tok == root) ? 1.0f : 0.0f;
            ac  += (s_alias[tok] == root) ? 1.0f : 0.0f;
            hd  += (float)((cmask >> tok) & 1ull);
        }
        float ov = 0.0f;
        #pragma unroll
        for (int s = 0; s < S_; s++) {
            if (((ffmask >> s) & 1) && ((wmask >> s_span[s]) & 1ull)) ov += 1.0f;
        }
        ov *= invdenom;
        const float inv16 = 1.0f / 16.0f;
        ex *= inv16; ac *= inv16; hd *= inv16;
        rp_mean = rp * inv16;

        regime = has ? (0.55f*hd + 0.2f*ov + 0.15f*ac + 0.1f*rp_mean)
                     : (0.45f*ex + 0.3f*ov + 0.1f*ac + 0.15f*rp_mean);
        sims = 0.25f*ex + 0.15f*ov + 0.35f*pos + 0.25f*regime;
        best_v = sims;
        hit06 = (sims >= 0.6f) ? 1.0f : 0.0f;
    }

    float best     = blockMax(best_v,  s_red, tid);
    float sum_sims = blockSum(sims,    s_red, tid);
    float sum_rp   = blockSum(rp_mean, s_red, tid);
    float sum_reg  = blockSum(regime,  s_red, tid);
    float cnt06    = blockSum(hit06,   s_red, tid);

    if (tid == 0) {
        const float invW = 1.0f / (float)W_;
        float mrp = sum_rp  * invW;
        float mrc = sum_reg * invW;
        float mean_sims = sum_sims * invW;
        float dmass = cnt06 * invW;
        float dcoh = 0.6f*mean_sims + 0.25f*mrp + 0.15f*mrc;
        float pattern_c = 1.0f - (0.6f*best + 0.2f*mrp + 0.2f*mrc);
        float contr = 0.2f*hidden_c + 0.2f*token_c + 0.6f*pattern_c;
        contr = fminf(fmaxf(contr, 0.0f), 1.0f);

        out[0 * NPAIR + pair_out] = contr;
        out[1 * NPAIR + pair_out] = future_shift;
        out[2 * NPAIR + pair_out] = sim;
        out[3 * NPAIR + pair_out] = hidden_c;
        out[4 * NPAIR + pair_out] = token_c;
        out[5 * NPAIR + pair_out] = pattern_c;
        out[6 * NPAIR + pair_out] = dmass;
        out[7 * NPAIR + pair_out] = dcoh;
    }
}

extern "C" void kernel_launch(void* const* d_in, const int* in_sizes, int n_in,
                              void* d_out, int out_size) {
    const float* hidden      = (const float*)d_in[0];
    const float* anchor_repr = (const float*)d_in[1];
    const int*   input_ids   = (const int*)d_in[2];
    const int*   anchor_end  = (const int*)d_in[3];
    float*       out         = (float*)d_out;
    ka_stream<<<2 * NPR, NT>>>(hidden, anchor_repr, anchor_end);
    kb_final<<<NPAIR, NT>>>(anchor_repr, input_ids, anchor_end, out);
}